// round 16
// baseline (speedup 1.0000x reference)
#include <cuda_runtime.h>
#include <cuda_fp16.h>

#define NMAX 50000
#define EMAX 800000
#define GMAX 2500
#define ETOT (EMAX + NMAX)
#define SCAN_B 512
#define SCAN_NB ((NMAX + SCAN_B - 1) / SCAN_B)   // 98
#define XPITCH 136                               // padded half-pitch (272B: conflict-free ldmatrix)

// ---- tensor-core helpers -------------------------------------------------------
#define LDSM4(r0, r1, r2, r3, a) \
  asm volatile("ldmatrix.sync.aligned.m8n8.x4.shared.b16 {%0,%1,%2,%3}, [%4];" \
               : "=r"(r0), "=r"(r1), "=r"(r2), "=r"(r3) : "r"(a))
#define LDSM4T(r0, r1, r2, r3, a) \
  asm volatile("ldmatrix.sync.aligned.m8n8.x4.trans.shared.b16 {%0,%1,%2,%3}, [%4];" \
               : "=r"(r0), "=r"(r1), "=r"(r2), "=r"(r3) : "r"(a))
#define MMA16816(d, a, b0, b1) \
  asm volatile("mma.sync.aligned.m16n8k16.row.col.f32.f16.f16.f32 " \
               "{%0,%1,%2,%3}, {%4,%5,%6,%7}, {%8,%9}, {%0,%1,%2,%3};" \
               : "+f"(d[0]), "+f"(d[1]), "+f"(d[2]), "+f"(d[3]) \
               : "r"(a[0]), "r"(a[1]), "r"(a[2]), "r"(a[3]), "r"(b0), "r"(b1))

// ---------------- scratch (device globals; no allocation allowed) ----------------
__device__ uint2 g_h16[NMAX * 32];     // per-layer hidden, fp16
__device__ float g_f0[NMAX * 64];      // layer output ping (fp32)
__device__ float g_f1[NMAX * 64];      // layer output pong
__device__ float g_att[NMAX * 4];      // per node: a_src0, a_src1, a_dst0, a_dst1
__device__ int   g_rp[NMAX + 1];       // CSR row_ptr (pre block-offset)
__device__ int   g_deg[NMAX];
__device__ int   g_fill[NMAX];
__device__ int   g_csrc[ETOT];         // CSR src indices
__device__ float g_gsum[GMAX];
__device__ float g_gcnt[GMAX];
__device__ int   g_bsum[SCAN_NB + 1];
__device__ int   g_boff[SCAN_NB + 1];

// ---------------- CSR build (dst is layer-invariant) + pool zero/count -----------
__global__ void k_init(int n, int g) {
  int i = blockIdx.x * blockDim.x + threadIdx.x;
  if (i < n) { g_deg[i] = 1; g_fill[i] = 0; }   // 1 = self loop
  if (i < g) { g_gsum[i] = 0.f; g_gcnt[i] = 0.f; }
}

__global__ void k_count(const int* __restrict__ ei, const int* __restrict__ batch,
                        int E, int n) {
  int i = blockIdx.x * blockDim.x + threadIdx.x;
  int E4 = E >> 2;
  if (i < E4) {
    int4 d = ((const int4*)(ei + E))[i];
    atomicAdd(&g_deg[d.x], 1);
    atomicAdd(&g_deg[d.y], 1);
    atomicAdd(&g_deg[d.z], 1);
    atomicAdd(&g_deg[d.w], 1);
  } else {
    int j = (E4 << 2) + (i - E4);
    if (j < E) atomicAdd(&g_deg[ei[E + j]], 1);
  }
  if (i < n) atomicAdd(&g_gcnt[batch[i]], 1.f);
}

__global__ void k_scan1(int n) {
  __shared__ int sh[SCAN_B];
  int t = threadIdx.x;
  int i = blockIdx.x * SCAN_B + t;
  int v = (i < n) ? g_deg[i] : 0;
  sh[t] = v;
  __syncthreads();
#pragma unroll
  for (int o = 1; o < SCAN_B; o <<= 1) {
    int x = (t >= o) ? sh[t - o] : 0;
    __syncthreads();
    sh[t] += x;
    __syncthreads();
  }
  if (i < n) g_rp[i] = sh[t] - v;
  if (t == SCAN_B - 1) g_bsum[blockIdx.x] = sh[t];
}

__global__ void k_scan2(int nb) {
  __shared__ int sh[128];
  int t = threadIdx.x;
  int v = (t < nb) ? g_bsum[t] : 0;
  sh[t] = v;
  __syncthreads();
#pragma unroll
  for (int o = 1; o < 128; o <<= 1) {
    int x = (t >= o) ? sh[t - o] : 0;
    __syncthreads();
    sh[t] += x;
    __syncthreads();
  }
  if (t < nb) g_boff[t] = sh[t] - v;
}

__global__ void k_scatter(const int* __restrict__ ei, int E, int n) {
  int i = blockIdx.x * blockDim.x + threadIdx.x;
  int E4 = E >> 2;
  if (i < E4) {
    int4 s = ((const int4*)ei)[i];
    int4 d = ((const int4*)(ei + E))[i];
    int px = atomicAdd(&g_fill[d.x], 1);
    int py = atomicAdd(&g_fill[d.y], 1);
    int pz = atomicAdd(&g_fill[d.z], 1);
    int pw = atomicAdd(&g_fill[d.w], 1);
    g_csrc[g_rp[d.x] + g_boff[d.x >> 9] + px] = s.x;
    g_csrc[g_rp[d.y] + g_boff[d.y >> 9] + py] = s.y;
    g_csrc[g_rp[d.z] + g_boff[d.z >> 9] + pz] = s.z;
    g_csrc[g_rp[d.w] + g_boff[d.w >> 9] + pw] = s.w;
  } else {
    int tail = E - (E4 << 2);
    int j = i - E4;
    if (j < tail) {
      int jj = (E4 << 2) + j;
      int s = ei[jj], d = ei[E + jj];
      int pos = atomicAdd(&g_fill[d], 1);
      g_csrc[g_rp[d] + g_boff[d >> 9] + pos] = s;
    } else {
      int v = j - tail;
      if (v < n) {
        int pos = atomicAdd(&g_fill[v], 1);
        g_csrc[g_rp[v] + g_boff[v >> 9] + pos] = v;   // self loop
      }
    }
  }
}

// ---------------- tensor-core GEMM + fused attention dots ------------------------
__global__ void k_gemm(const float* __restrict__ Xin, int insel,
                       const float* __restrict__ W,
                       const float* __restrict__ asrc,
                       const float* __restrict__ adst, int n, int fin) {
  const float* X = Xin ? Xin : (insel ? g_f1 : g_f0);
  __shared__ half xs[32 * XPITCH];     // X tile, later D tile
  __shared__ half ws[128 * XPITCH];    // W fp16
  int tid = threadIdx.x;
  int lane = tid & 31, wid = tid >> 5;
  int row0 = blockIdx.x * 32;
  int fin4 = fin >> 2;

  const float4* X4 = (const float4*)X;
  for (int i = tid; i < 32 * fin4; i += 128) {
    int r = i / fin4, k4 = i - r * fin4;
    float4 v = make_float4(0.f, 0.f, 0.f, 0.f);
    if (row0 + r < n) v = X4[(row0 + r) * fin4 + k4];
    *(half2*)&xs[r * XPITCH + k4 * 4]     = __floats2half2_rn(v.x, v.y);
    *(half2*)&xs[r * XPITCH + k4 * 4 + 2] = __floats2half2_rn(v.z, v.w);
  }
  for (int i = tid; i < fin * 32; i += 128) {
    int k = i >> 5, c4 = i & 31;
    float4 v = *(const float4*)&W[k * 128 + c4 * 4];
    *(half2*)&ws[k * XPITCH + c4 * 4]     = __floats2half2_rn(v.x, v.y);
    *(half2*)&ws[k * XPITCH + c4 * 4 + 2] = __floats2half2_rn(v.z, v.w);
  }
  __syncthreads();

  unsigned xs_u = (unsigned)__cvta_generic_to_shared(xs);
  unsigned ws_u = (unsigned)__cvta_generic_to_shared(ws);

  float acc[2][4][4];
#pragma unroll
  for (int m = 0; m < 2; m++)
#pragma unroll
    for (int t = 0; t < 4; t++) { acc[m][t][0] = acc[m][t][1] = acc[m][t][2] = acc[m][t][3] = 0.f; }

  int arow = lane & 15;
  int akof = (lane >> 4) << 3;
  int bkr  = (lane & 7) + (((lane >> 3) & 1) << 3);
  int bcof = ((lane >> 4) & 1) << 3;
  int colw = wid * 32;

  for (int ks = 0; ks < fin; ks += 16) {
    unsigned a0[4], a1[4], b0[4], b1[4];
    LDSM4(a0[0], a0[1], a0[2], a0[3],
          xs_u + (unsigned)((arow * XPITCH + ks + akof) * 2));
    LDSM4(a1[0], a1[1], a1[2], a1[3],
          xs_u + (unsigned)(((16 + arow) * XPITCH + ks + akof) * 2));
    LDSM4T(b0[0], b0[1], b0[2], b0[3],
           ws_u + (unsigned)(((ks + bkr) * XPITCH + colw + bcof) * 2));
    LDSM4T(b1[0], b1[1], b1[2], b1[3],
           ws_u + (unsigned)(((ks + bkr) * XPITCH + colw + 16 + bcof) * 2));
    MMA16816(acc[0][0], a0, b0[0], b0[1]);
    MMA16816(acc[0][1], a0, b0[2], b0[3]);
    MMA16816(acc[0][2], a0, b1[0], b1[1]);
    MMA16816(acc[0][3], a0, b1[2], b1[3]);
    MMA16816(acc[1][0], a1, b0[0], b0[1]);
    MMA16816(acc[1][1], a1, b0[2], b0[3]);
    MMA16816(acc[1][2], a1, b1[0], b1[1]);
    MMA16816(acc[1][3], a1, b1[2], b1[3]);
  }
  __syncthreads();

  int g = lane >> 2, t2 = (lane & 3) * 2;
#pragma unroll
  for (int mt = 0; mt < 2; mt++)
#pragma unroll
    for (int nt = 0; nt < 4; nt++) {
      int col = colw + nt * 8 + t2;
      *(half2*)&xs[(mt * 16 + g) * XPITCH + col] =
          __floats2half2_rn(acc[mt][nt][0], acc[mt][nt][1]);
      *(half2*)&xs[(mt * 16 + g + 8) * XPITCH + col] =
          __floats2half2_rn(acc[mt][nt][2], acc[mt][nt][3]);
    }
  __syncthreads();

  float4 as4 = *(const float4*)&asrc[lane * 4];
  float4 ad4 = *(const float4*)&adst[lane * 4];
#pragma unroll
  for (int r = 0; r < 8; r++) {
    int rl = wid * 8 + r;
    int row = row0 + rl;
    uint2 hp = *(uint2*)&xs[rl * XPITCH + lane * 4];
    float2 f0 = __half22float2(*(half2*)&hp.x);
    float2 f1 = __half22float2(*(half2*)&hp.y);
    float ss = f0.x * as4.x + f0.y * as4.y + f1.x * as4.z + f1.y * as4.w;
    float sd = f0.x * ad4.x + f0.y * ad4.y + f1.x * ad4.z + f1.y * ad4.w;
#pragma unroll
    for (int o = 8; o; o >>= 1) {
      ss += __shfl_xor_sync(0xffffffffu, ss, o);
      sd += __shfl_xor_sync(0xffffffffu, sd, o);
    }
    float ss1 = __shfl_sync(0xffffffffu, ss, 16);
    float sd1 = __shfl_sync(0xffffffffu, sd, 16);
    if (row < n) {
      g_h16[row * 32 + lane] = hp;
      if (lane == 0) *(float4*)&g_att[4 * row] = make_float4(ss, ss1, sd, sd1);
    }
  }
}

// ---------------- softmax + aggregate + head-mean + bias + relu ------------------
__global__ void k_agg(const float* __restrict__ bias, int outsel, int n,
                      const float* __restrict__ lw, const int* __restrict__ batch) {
  float* OUT = outsel ? g_f1 : g_f0;
  int v = blockIdx.x * 8 + (threadIdx.x >> 5);
  int lane = threadIdx.x & 31;
  if (v >= n) return;
  int rs = g_rp[v] + g_boff[v >> 9];
  int re = rs + g_deg[v];
  float2 adv = *(const float2*)&g_att[4 * v + 2];
  bool head1 = lane >= 16;

  float s0 = 0.f, s1 = 0.f;
  float4 acc = make_float4(0.f, 0.f, 0.f, 0.f);
  for (int base = rs; base < re; base += 32) {
    int jj = base + lane;
    int s_l = 0;
    float x0 = 0.f, x1 = 0.f;
    if (jj < re) {
      s_l = g_csrc[jj];                                 // coalesced
      float2 as = *(const float2*)&g_att[4 * s_l];      // independent gathers
      float e0 = as.x + adv.x; e0 = fmaxf(e0, 0.2f * e0);
      float e1 = as.y + adv.y; e1 = fmaxf(e1, 0.2f * e1);
      x0 = __expf(e0); x1 = __expf(e1);
    }
    s0 += x0; s1 += x1;
    int cnt = min(re - base, 32);
#pragma unroll 4
    for (int k = 0; k < cnt; k++) {
      int s = __shfl_sync(0xffffffffu, s_l, k);
      float xa = __shfl_sync(0xffffffffu, x0, k);
      float xb = __shfl_sync(0xffffffffu, x1, k);
      float xw = head1 ? xb : xa;
      uint2 hp = g_h16[s * 32 + lane];                  // independent 256B/warp
      float2 f0 = __half22float2(*(half2*)&hp.x);
      float2 f1 = __half22float2(*(half2*)&hp.y);
      acc.x += xw * f0.x; acc.y += xw * f0.y;
      acc.z += xw * f1.x; acc.w += xw * f1.y;
    }
  }
#pragma unroll
  for (int o = 16; o; o >>= 1) {
    s0 += __shfl_xor_sync(0xffffffffu, s0, o);
    s1 += __shfl_xor_sync(0xffffffffu, s1, o);
  }
  float r0 = 0.5f / fmaxf(s0, 1e-16f);
  float r1 = 0.5f / fmaxf(s1, 1e-16f);
  float rw = head1 ? r1 : r0;
  acc.x *= rw; acc.y *= rw; acc.z *= rw; acc.w *= rw;
  float px = __shfl_xor_sync(0xffffffffu, acc.x, 16);
  float py = __shfl_xor_sync(0xffffffffu, acc.y, 16);
  float pz = __shfl_xor_sync(0xffffffffu, acc.z, 16);
  float pw = __shfl_xor_sync(0xffffffffu, acc.w, 16);
  float pdot = 0.f;
  if (!head1) {
    float4 b4 = *(const float4*)&bias[lane * 4];
    float4 o;
    o.x = fmaxf(acc.x + px + b4.x, 0.f);
    o.y = fmaxf(acc.y + py + b4.y, 0.f);
    o.z = fmaxf(acc.z + pz + b4.z, 0.f);
    o.w = fmaxf(acc.w + pw + b4.w, 0.f);
    if (!lw) {
      *(float4*)&OUT[v * 64 + lane * 4] = o;
    } else {
      float4 w4 = *(const float4*)&lw[lane * 4];
      pdot = o.x * w4.x + o.y * w4.y + o.z * w4.z + o.w * w4.w;
    }
  }
  if (lw) {
#pragma unroll
    for (int o = 8; o; o >>= 1) pdot += __shfl_xor_sync(0xffffffffu, pdot, o);
    if (lane == 0) atomicAdd(&g_gsum[batch[v]], pdot);
  }
}

// ---------------- final linear -----------------------------------------
__global__ void k_final(const float* __restrict__ lb, float* __restrict__ out, int g) {
  int i = blockIdx.x * blockDim.x + threadIdx.x;
  if (i < g) out[i] = g_gsum[i] / fmaxf(g_gcnt[i], 1.f) + lb[0];
}

// ---------------- launch ----------------------------------------------------------
extern "C" void kernel_launch(void* const* d_in, const int* in_sizes, int n_in,
                              void* d_out, int out_size) {
  int base;
  const int *ei, *bat;
  int Esz;
  if (in_sizes[1] > 1000000) {          // dict order: x, edge_index, batch, ...
    ei = (const int*)d_in[1];
    bat = (const int*)d_in[2];
    base = 3;
    Esz = in_sizes[1];
  } else {                               // signature order
    base = 1;
    ei = (const int*)d_in[15];
    bat = (const int*)d_in[16];
    Esz = in_sizes[15];
  }
  const float* x   = (const float*)d_in[0];
  const float* W1  = (const float*)d_in[base + 0];
  const float* as1 = (const float*)d_in[base + 1];
  const float* ad1 = (const float*)d_in[base + 2];
  const float* b1  = (const float*)d_in[base + 3];
  const float* W2  = (const float*)d_in[base + 4];
  const float* as2 = (const float*)d_in[base + 5];
  const float* ad2 = (const float*)d_in[base + 6];
  const float* b2  = (const float*)d_in[base + 7];
  const float* W3  = (const float*)d_in[base + 8];
  const float* as3 = (const float*)d_in[base + 9];
  const float* ad3 = (const float*)d_in[base + 10];
  const float* b3  = (const float*)d_in[base + 11];
  const float* lw  = (const float*)d_in[base + 12];
  const float* lb  = (const float*)d_in[base + 13];

  int n = in_sizes[0] / 128;
  int E = Esz / 2;
  int G = out_size;

  // side stream + fork/join events: created lazily on the FIRST call (the
  // uncaptured correctness run), reused every call -> identical captured graph.
  static cudaStream_t s_side = nullptr;
  static cudaEvent_t ev_fork = nullptr, ev_join = nullptr;
  if (!s_side) {
    cudaStreamCreateWithFlags(&s_side, cudaStreamNonBlocking);
    cudaEventCreateWithFlags(&ev_fork, cudaEventDisableTiming);
    cudaEventCreateWithFlags(&ev_join, cudaEventDisableTiming);
  }

  const int tb = 256;
  int gb = (n + 31) / 32;
  int wg = (n + 7) / 8;
  int E4 = E >> 2;
  int tailE = E - (E4 << 2);
  int nb = (n + SCAN_B - 1) / SCAN_B;
  int cntGrid = ((E4 + tailE > n ? E4 + tailE : n) + tb - 1) / tb;

  // fork: CSR chain on side stream, concurrent with gemm layer 1 on main
  cudaEventRecord(ev_fork, 0);
  cudaStreamWaitEvent(s_side, ev_fork, 0);
  k_init<<<(n + tb - 1) / tb, tb, 0, s_side>>>(n, G);
  k_count<<<cntGrid, tb, 0, s_side>>>(ei, bat, E, n);
  k_scan1<<<nb, SCAN_B, 0, s_side>>>(n);
  k_scan2<<<1, 128, 0, s_side>>>(nb);
  k_scatter<<<(E4 + tailE + n + tb - 1) / tb, tb, 0, s_side>>>(ei, E, n);
  cudaEventRecord(ev_join, s_side);

  k_gemm<<<gb, 128>>>(x, 0, W1, as1, ad1, n, 128);

  // join: agg1 needs both h/att (main) and CSR (side)
  cudaStreamWaitEvent(0, ev_join, 0);
  k_agg<<<wg, 256>>>(b1, 0, n, nullptr, nullptr);
  k_gemm<<<gb, 128>>>(nullptr, 0, W2, as2, ad2, n, 64);
  k_agg<<<wg, 256>>>(b2, 1, n, nullptr, nullptr);
  k_gemm<<<gb, 128>>>(nullptr, 1, W3, as3, ad3, n, 64);
  k_agg<<<wg, 256>>>(b3, 0, n, lw, bat);        // fused global-mean-pool dot

  k_final<<<(G + tb - 1) / tb, tb>>>(lb, (float*)d_out, G);
}

// round 17
// speedup vs baseline: 1.0373x; 1.0373x over previous
#include <cuda_runtime.h>
#include <cuda_fp16.h>

#define NMAX 50000
#define EMAX 800000
#define GMAX 2500
#define ETOT (EMAX + NMAX)
#define SCAN_B 512
#define SCAN_NB ((NMAX + SCAN_B - 1) / SCAN_B)   // 98
#define XPITCH 136                               // padded half-pitch (272B: conflict-free ldmatrix)

// ---- tensor-core helpers -------------------------------------------------------
#define LDSM4(r0, r1, r2, r3, a) \
  asm volatile("ldmatrix.sync.aligned.m8n8.x4.shared.b16 {%0,%1,%2,%3}, [%4];" \
               : "=r"(r0), "=r"(r1), "=r"(r2), "=r"(r3) : "r"(a))
#define LDSM4T(r0, r1, r2, r3, a) \
  asm volatile("ldmatrix.sync.aligned.m8n8.x4.trans.shared.b16 {%0,%1,%2,%3}, [%4];" \
               : "=r"(r0), "=r"(r1), "=r"(r2), "=r"(r3) : "r"(a))
#define MMA16816(d, a, b0, b1) \
  asm volatile("mma.sync.aligned.m16n8k16.row.col.f32.f16.f16.f32 " \
               "{%0,%1,%2,%3}, {%4,%5,%6,%7}, {%8,%9}, {%0,%1,%2,%3};" \
               : "+f"(d[0]), "+f"(d[1]), "+f"(d[2]), "+f"(d[3]) \
               : "r"(a[0]), "r"(a[1]), "r"(a[2]), "r"(a[3]), "r"(b0), "r"(b1))

// ---------------- scratch (device globals; zero-initialized at module load) ------
// INVARIANT (zero-at-exit): g_deg, g_fill, g_gsum, g_gcnt, g_ctr1 are zero on
// entry to every call; k_final / k_scan1's last block restore them.
__device__ uint2 g_h16[NMAX * 32];     // per-layer hidden, fp16
__device__ float g_f0[NMAX * 64];      // layer output ping (fp32)
__device__ float g_f1[NMAX * 64];      // layer output pong
__device__ float g_att[NMAX * 4];      // per node: a_src0, a_src1, a_dst0, a_dst1
__device__ int   g_rp[NMAX + 1];       // CSR row_ptr (pre block-offset)
__device__ int   g_deg[NMAX];          // edge-only degree (self loop = +1 implicit)
__device__ int   g_fill[NMAX];
__device__ int   g_csrc[ETOT];         // CSR src indices
__device__ float g_gsum[GMAX];
__device__ float g_gcnt[GMAX];
__device__ int   g_bsum[SCAN_NB + 1];
__device__ int   g_boff[SCAN_NB + 1];
__device__ int   g_ctr1;               // scan last-block ticket
__device__ half  g_w16[128 * 128 + 64 * 128 + 64 * 128];  // W1|W2|W3 fp16

// ---------------- one-time-per-call W fp32->fp16 conversion ----------------------
__global__ void k_wconv(const float* __restrict__ W1, const float* __restrict__ W2,
                        const float* __restrict__ W3) {
  int i = blockIdx.x * blockDim.x + threadIdx.x;   // half2 index
  if (i < 8192) {
    float2 v = ((const float2*)W1)[i];
    *(half2*)&g_w16[2 * i] = __floats2half2_rn(v.x, v.y);
  } else if (i < 12288) {
    int j = i - 8192;
    float2 v = ((const float2*)W2)[j];
    *(half2*)&g_w16[16384 + 2 * j] = __floats2half2_rn(v.x, v.y);
  } else if (i < 16384) {
    int j = i - 12288;
    float2 v = ((const float2*)W3)[j];
    *(half2*)&g_w16[24576 + 2 * j] = __floats2half2_rn(v.x, v.y);
  }
}

// --------- deg count (4 edges/thread) + graph-size count (deg/gcnt zero on entry)
__global__ void k_count(const int* __restrict__ ei, const int* __restrict__ batch,
                        int E, int n) {
  int i = blockIdx.x * blockDim.x + threadIdx.x;
  int E4 = E >> 2;
  if (i < E4) {
    int4 d = ((const int4*)(ei + E))[i];
    atomicAdd(&g_deg[d.x], 1);
    atomicAdd(&g_deg[d.y], 1);
    atomicAdd(&g_deg[d.z], 1);
    atomicAdd(&g_deg[d.w], 1);
  } else {
    int j = (E4 << 2) + (i - E4);
    if (j < E) atomicAdd(&g_deg[ei[E + j]], 1);
  }
  if (i < n) atomicAdd(&g_gcnt[batch[i]], 1.f);
}

// ---------- exclusive scan of (deg+1); LAST block scans the block sums -----------
// (ticket-fused form measured neutral vs separate scan2 in the same noise regime)
__global__ void k_scan1(int n, int nb) {
  __shared__ int sh[SCAN_B];
  __shared__ int lastblk;
  int t = threadIdx.x;
  int i = blockIdx.x * SCAN_B + t;
  int v = (i < n) ? (g_deg[i] + 1) : 0;        // +1 = self loop
  sh[t] = v;
  __syncthreads();
#pragma unroll
  for (int o = 1; o < SCAN_B; o <<= 1) {
    int x = (t >= o) ? sh[t - o] : 0;
    __syncthreads();
    sh[t] += x;
    __syncthreads();
  }
  if (i < n) g_rp[i] = sh[t] - v;              // exclusive, pre block-offset
  if (t == SCAN_B - 1) {
    g_bsum[blockIdx.x] = sh[t];
    __threadfence();                            // bsum visible before ticket
    int r = atomicAdd(&g_ctr1, 1);
    lastblk = (r == (int)gridDim.x - 1);
  }
  __syncthreads();
  if (lastblk) {
    int v2 = (t < nb) ? g_bsum[t] : 0;
    sh[t] = v2;
    __syncthreads();
#pragma unroll
    for (int o = 1; o < SCAN_B; o <<= 1) {
      int x = (t >= o) ? sh[t - o] : 0;
      __syncthreads();
      sh[t] += x;
      __syncthreads();
    }
    if (t < nb) g_boff[t] = sh[t] - v2;
    if (t == 0) g_ctr1 = 0;                    // restore invariant
  }
}

// 4 edges per thread; self-loops appended in the same grid (fill zero on entry).
__global__ void k_scatter(const int* __restrict__ ei, int E, int n) {
  int i = blockIdx.x * blockDim.x + threadIdx.x;
  int E4 = E >> 2;
  if (i < E4) {
    int4 s = ((const int4*)ei)[i];
    int4 d = ((const int4*)(ei + E))[i];
    int px = atomicAdd(&g_fill[d.x], 1);
    int py = atomicAdd(&g_fill[d.y], 1);
    int pz = atomicAdd(&g_fill[d.z], 1);
    int pw = atomicAdd(&g_fill[d.w], 1);
    g_csrc[g_rp[d.x] + g_boff[d.x >> 9] + px] = s.x;
    g_csrc[g_rp[d.y] + g_boff[d.y >> 9] + py] = s.y;
    g_csrc[g_rp[d.z] + g_boff[d.z >> 9] + pz] = s.z;
    g_csrc[g_rp[d.w] + g_boff[d.w >> 9] + pw] = s.w;
  } else {
    int tail = E - (E4 << 2);
    int j = i - E4;
    if (j < tail) {
      int jj = (E4 << 2) + j;
      int s = ei[jj], d = ei[E + jj];
      int pos = atomicAdd(&g_fill[d], 1);
      g_csrc[g_rp[d] + g_boff[d >> 9] + pos] = s;
    } else {
      int v = j - tail;
      if (v < n) {
        int pos = atomicAdd(&g_fill[v], 1);
        g_csrc[g_rp[v] + g_boff[v >> 9] + pos] = v;   // self loop
      }
    }
  }
}

// ---------------- tensor-core GEMM + fused attention dots ------------------------
// W already fp16 in g_w16 (halved staging traffic vs fp32).
__global__ void k_gemm(const float* __restrict__ Xin, int insel,
                       const half* __restrict__ Wh,
                       const float* __restrict__ asrc,
                       const float* __restrict__ adst, int n, int fin) {
  const float* X = Xin ? Xin : (insel ? g_f1 : g_f0);
  __shared__ half xs[32 * XPITCH];     // X tile, later D tile
  __shared__ half ws[128 * XPITCH];    // W fp16
  int tid = threadIdx.x;
  int lane = tid & 31, wid = tid >> 5;
  int row0 = blockIdx.x * 32;
  int fin4 = fin >> 2;

  const float4* X4 = (const float4*)X;
  for (int i = tid; i < 32 * fin4; i += 128) {
    int r = i / fin4, k4 = i - r * fin4;
    float4 v = make_float4(0.f, 0.f, 0.f, 0.f);
    if (row0 + r < n) v = X4[(row0 + r) * fin4 + k4];
    *(half2*)&xs[r * XPITCH + k4 * 4]     = __floats2half2_rn(v.x, v.y);
    *(half2*)&xs[r * XPITCH + k4 * 4 + 2] = __floats2half2_rn(v.z, v.w);
  }
  // stage W fp16: 8 halves (uint4) per load; row k = i>>4, chunk c8 = i&15
  const uint4* W4 = (const uint4*)Wh;
  for (int i = tid; i < fin * 16; i += 128) {
    int k = i >> 4, c8 = i & 15;
    *(uint4*)&ws[k * XPITCH + c8 * 8] = W4[i];
  }
  __syncthreads();

  unsigned xs_u = (unsigned)__cvta_generic_to_shared(xs);
  unsigned ws_u = (unsigned)__cvta_generic_to_shared(ws);

  float acc[2][4][4];
#pragma unroll
  for (int m = 0; m < 2; m++)
#pragma unroll
    for (int t = 0; t < 4; t++) { acc[m][t][0] = acc[m][t][1] = acc[m][t][2] = acc[m][t][3] = 0.f; }

  int arow = lane & 15;
  int akof = (lane >> 4) << 3;
  int bkr  = (lane & 7) + (((lane >> 3) & 1) << 3);
  int bcof = ((lane >> 4) & 1) << 3;
  int colw = wid * 32;

  for (int ks = 0; ks < fin; ks += 16) {
    unsigned a0[4], a1[4], b0[4], b1[4];
    LDSM4(a0[0], a0[1], a0[2], a0[3],
          xs_u + (unsigned)((arow * XPITCH + ks + akof) * 2));
    LDSM4(a1[0], a1[1], a1[2], a1[3],
          xs_u + (unsigned)(((16 + arow) * XPITCH + ks + akof) * 2));
    LDSM4T(b0[0], b0[1], b0[2], b0[3],
           ws_u + (unsigned)(((ks + bkr) * XPITCH + colw + bcof) * 2));
    LDSM4T(b1[0], b1[1], b1[2], b1[3],
           ws_u + (unsigned)(((ks + bkr) * XPITCH + colw + 16 + bcof) * 2));
    MMA16816(acc[0][0], a0, b0[0], b0[1]);
    MMA16816(acc[0][1], a0, b0[2], b0[3]);
    MMA16816(acc[0][2], a0, b1[0], b1[1]);
    MMA16816(acc[0][3], a0, b1[2], b1[3]);
    MMA16816(acc[1][0], a1, b0[0], b0[1]);
    MMA16816(acc[1][1], a1, b0[2], b0[3]);
    MMA16816(acc[1][2], a1, b1[0], b1[1]);
    MMA16816(acc[1][3], a1, b1[2], b1[3]);
  }
  __syncthreads();

  int g = lane >> 2, t2 = (lane & 3) * 2;
#pragma unroll
  for (int mt = 0; mt < 2; mt++)
#pragma unroll
    for (int nt = 0; nt < 4; nt++) {
      int col = colw + nt * 8 + t2;
      *(half2*)&xs[(mt * 16 + g) * XPITCH + col] =
          __floats2half2_rn(acc[mt][nt][0], acc[mt][nt][1]);
      *(half2*)&xs[(mt * 16 + g + 8) * XPITCH + col] =
          __floats2half2_rn(acc[mt][nt][2], acc[mt][nt][3]);
    }
  __syncthreads();

  float4 as4 = *(const float4*)&asrc[lane * 4];
  float4 ad4 = *(const float4*)&adst[lane * 4];
#pragma unroll
  for (int r = 0; r < 8; r++) {
    int rl = wid * 8 + r;
    int row = row0 + rl;
    uint2 hp = *(uint2*)&xs[rl * XPITCH + lane * 4];
    float2 f0 = __half22float2(*(half2*)&hp.x);
    float2 f1 = __half22float2(*(half2*)&hp.y);
    float ss = f0.x * as4.x + f0.y * as4.y + f1.x * as4.z + f1.y * as4.w;
    float sd = f0.x * ad4.x + f0.y * ad4.y + f1.x * ad4.z + f1.y * ad4.w;
#pragma unroll
    for (int o = 8; o; o >>= 1) {
      ss += __shfl_xor_sync(0xffffffffu, ss, o);
      sd += __shfl_xor_sync(0xffffffffu, sd, o);
    }
    float ss1 = __shfl_sync(0xffffffffu, ss, 16);
    float sd1 = __shfl_sync(0xffffffffu, sd, 16);
    if (row < n) {
      g_h16[row * 32 + lane] = hp;
      if (lane == 0) *(float4*)&g_att[4 * row] = make_float4(ss, ss1, sd, sd1);
    }
  }
}

// ---------------- softmax + aggregate + head-mean + bias + relu ------------------
__global__ void k_agg(const float* __restrict__ bias, int outsel, int n,
                      const float* __restrict__ lw, const int* __restrict__ batch) {
  float* OUT = outsel ? g_f1 : g_f0;
  int v = blockIdx.x * 8 + (threadIdx.x >> 5);
  int lane = threadIdx.x & 31;
  if (v >= n) return;
  int rs = g_rp[v] + g_boff[v >> 9];
  int re = rs + g_deg[v] + 1;                  // +1 self loop
  float2 adv = *(const float2*)&g_att[4 * v + 2];
  bool head1 = lane >= 16;

  float s0 = 0.f, s1 = 0.f;
  float4 acc = make_float4(0.f, 0.f, 0.f, 0.f);
  for (int base = rs; base < re; base += 32) {
    int jj = base + lane;
    int s_l = 0;
    float x0 = 0.f, x1 = 0.f;
    if (jj < re) {
      s_l = g_csrc[jj];                                 // coalesced
      float2 as = *(const float2*)&g_att[4 * s_l];      // independent gathers
      float e0 = as.x + adv.x; e0 = fmaxf(e0, 0.2f * e0);
      float e1 = as.y + adv.y; e1 = fmaxf(e1, 0.2f * e1);
      x0 = __expf(e0); x1 = __expf(e1);
    }
    s0 += x0; s1 += x1;
    int cnt = min(re - base, 32);
#pragma unroll 4
    for (int k = 0; k < cnt; k++) {
      int s = __shfl_sync(0xffffffffu, s_l, k);
      float xa = __shfl_sync(0xffffffffu, x0, k);
      float xb = __shfl_sync(0xffffffffu, x1, k);
      float xw = head1 ? xb : xa;
      uint2 hp = g_h16[s * 32 + lane];                  // independent 256B/warp
      float2 f0 = __half22float2(*(half2*)&hp.x);
      float2 f1 = __half22float2(*(half2*)&hp.y);
      acc.x += xw * f0.x; acc.y += xw * f0.y;
      acc.z += xw * f1.x; acc.w += xw * f1.y;
    }
  }
#pragma unroll
  for (int o = 16; o; o >>= 1) {
    s0 += __shfl_xor_sync(0xffffffffu, s0, o);
    s1 += __shfl_xor_sync(0xffffffffu, s1, o);
  }
  float r0 = 0.5f / fmaxf(s0, 1e-16f);
  float r1 = 0.5f / fmaxf(s1, 1e-16f);
  float rw = head1 ? r1 : r0;
  acc.x *= rw; acc.y *= rw; acc.z *= rw; acc.w *= rw;
  float px = __shfl_xor_sync(0xffffffffu, acc.x, 16);
  float py = __shfl_xor_sync(0xffffffffu, acc.y, 16);
  float pz = __shfl_xor_sync(0xffffffffu, acc.z, 16);
  float pw = __shfl_xor_sync(0xffffffffu, acc.w, 16);
  float pdot = 0.f;
  if (!head1) {
    float4 b4 = *(const float4*)&bias[lane * 4];
    float4 o;
    o.x = fmaxf(acc.x + px + b4.x, 0.f);
    o.y = fmaxf(acc.y + py + b4.y, 0.f);
    o.z = fmaxf(acc.z + pz + b4.z, 0.f);
    o.w = fmaxf(acc.w + pw + b4.w, 0.f);
    if (!lw) {
      *(float4*)&OUT[v * 64 + lane * 4] = o;
    } else {
      float4 w4 = *(const float4*)&lw[lane * 4];
      pdot = o.x * w4.x + o.y * w4.y + o.z * w4.z + o.w * w4.w;
    }
  }
  if (lw) {
#pragma unroll
    for (int o = 8; o; o >>= 1) pdot += __shfl_xor_sync(0xffffffffu, pdot, o);
    if (lane == 0) atomicAdd(&g_gsum[batch[v]], pdot);
  }
}

// ---------------- final linear + zero-at-exit -------------------------------------
__global__ void k_final(const float* __restrict__ lb, float* __restrict__ out,
                        int g, int n) {
  int i = blockIdx.x * blockDim.x + threadIdx.x;
  if (i < g) {
    out[i] = g_gsum[i] / fmaxf(g_gcnt[i], 1.f) + lb[0];
    g_gsum[i] = 0.f;                            // zero-at-exit
    g_gcnt[i] = 0.f;
  }
  if (i < n) { g_deg[i] = 0; g_fill[i] = 0; }   // zero-at-exit
}

// ---------------- launch ----------------------------------------------------------
extern "C" void kernel_launch(void* const* d_in, const int* in_sizes, int n_in,
                              void* d_out, int out_size) {
  int base;
  const int *ei, *bat;
  int Esz;
  if (in_sizes[1] > 1000000) {          // dict order: x, edge_index, batch, ...
    ei = (const int*)d_in[1];
    bat = (const int*)d_in[2];
    base = 3;
    Esz = in_sizes[1];
  } else {                               // signature order
    base = 1;
    ei = (const int*)d_in[15];
    bat = (const int*)d_in[16];
    Esz = in_sizes[15];
  }
  const float* x   = (const float*)d_in[0];
  const float* W1  = (const float*)d_in[base + 0];
  const float* as1 = (const float*)d_in[base + 1];
  const float* ad1 = (const float*)d_in[base + 2];
  const float* b1  = (const float*)d_in[base + 3];
  const float* W2  = (const float*)d_in[base + 4];
  const float* as2 = (const float*)d_in[base + 5];
  const float* ad2 = (const float*)d_in[base + 6];
  const float* b2  = (const float*)d_in[base + 7];
  const float* W3  = (const float*)d_in[base + 8];
  const float* as3 = (const float*)d_in[base + 9];
  const float* ad3 = (const float*)d_in[base + 10];
  const float* b3  = (const float*)d_in[base + 11];
  const float* lw  = (const float*)d_in[base + 12];
  const float* lb  = (const float*)d_in[base + 13];

  int n = in_sizes[0] / 128;
  int E = Esz / 2;
  int G = out_size;

  const int tb = 256;
  int gb = (n + 31) / 32;
  int wg = (n + 7) / 8;
  int E4 = E >> 2;
  int tailE = E - (E4 << 2);
  int nb = (n + SCAN_B - 1) / SCAN_B;
  int cntGrid = ((E4 + tailE > n ? E4 + tailE : n) + tb - 1) / tb;

  // W -> fp16 once; CSR build (deg/fill/gsum/gcnt zero on entry: zero-at-exit)
  k_wconv<<<64, 256>>>(W1, W2, W3);
  k_count<<<cntGrid, tb>>>(ei, bat, E, n);
  k_scan1<<<nb, SCAN_B>>>(n, nb);
  k_scatter<<<(E4 + tailE + n + tb - 1) / tb, tb>>>(ei, E, n);

  const half* w16 = nullptr;   // device-symbol offsets resolved via kernel arg
  // g_w16 layout: W1 @ 0, W2 @ 16384, W3 @ 24576
  half* w16base;
  cudaGetSymbolAddress((void**)&w16base, g_w16);
  (void)w16;

  k_gemm<<<gb, 128>>>(x, 0, w16base, as1, ad1, n, 128);
  k_agg<<<wg, 256>>>(b1, 0, n, nullptr, nullptr);
  k_gemm<<<gb, 128>>>(nullptr, 0, w16base + 16384, as2, ad2, n, 64);
  k_agg<<<wg, 256>>>(b2, 1, n, nullptr, nullptr);
  k_gemm<<<gb, 128>>>(nullptr, 1, w16base + 24576, as3, ad3, n, 64);
  k_agg<<<wg, 256>>>(b3, 0, n, lw, bat);        // fused global-mean-pool dot

  k_final<<<((n > G ? n : G) + tb - 1) / tb, tb>>>(lb, (float*)d_out, G, n);
}